// round 10
// baseline (speedup 1.0000x reference)
#include <cuda_runtime.h>
#include <math.h>

#define BATCH 2048
#define TSTEPS 1000
#define NI 40
#define NH 16
#define NR 32
#define NO 2

#define CHUNKS 10
#define CHLEN (TSTEPS / CHUNKS)   // 100 steps = 50 pairs per warp
#define NPAIR (CHLEN / 2)         // 50

#define OUT_LOSS 0
#define OUT_D2   1
#define OUT_CORR (1 + (size_t)BATCH * TSTEPS * NO)
#define OUT_TOT  (OUT_CORR + 1)

// 262 MB scratch: pre-scaled dendritic currents pc[b][t][r] = (1-beta_r)*cur
__device__ __align__(16) float g_cur[(size_t)BATCH * TSTEPS * NR];
// 4 MB scratch: packed spike ballots per recur-warp (4 batches) per step
__device__ __align__(16) uint2 g_ball[(size_t)(BATCH / 4) * TSTEPS];

__device__ __forceinline__ void fma2(unsigned long long& acc,
                                     unsigned long long a,
                                     unsigned long long b) {
    asm("fma.rn.f32x2 %0, %1, %2, %3;" : "=l"(acc) : "l"(a), "l"(b), "l"(acc));
}
__device__ __forceinline__ unsigned long long packf2(float lo, float hi) {
    unsigned long long r;
    asm("mov.b64 %0, {%1, %2};" : "=l"(r) : "f"(lo), "f"(hi));
    return r;
}
__device__ __forceinline__ void unpackf2(unsigned long long v, float& lo, float& hi) {
    asm("mov.b64 {%0, %1}, %2;" : "=f"(lo), "=f"(hi) : "l"(v));
}
__device__ __forceinline__ float sigm(float v) { return 1.0f / (1.0f + expf(-v)); }

// ---------------- Kernel A: masked matvec, direct uniform LDG ---------------
// warp w: batch b = w/CHUNKS, steps [c*CHLEN, (c+1)*CHLEN), 2 steps per iter.
// lane = half*16 + rl: half = step parity in pair, rl owns rows 2rl, 2rl+1.
// x_t is read straight from global with half-warp-uniform LDG.128 — the L1
// return path broadcasts; no smem staging at all.
__global__ __launch_bounds__(128) void matvec_kernel(
    const float* __restrict__ x,     // [B, T, NI]
    const float* __restrict__ W1,    // [NR, NI]
    const float* __restrict__ mask,  // [NR, NI]
    const float* __restrict__ tau_n, // [NR]
    float*       __restrict__ out)
{
    if (blockIdx.x == 0 && threadIdx.x == 0) {
        out[OUT_LOSS] = 0.0f;
        int c = 0;
        for (int t = 0; t < TSTEPS; ++t)
            if (t > 10 && ((t - 10) % 15) > 5) c++;
        out[OUT_CORR] = 0.0f;
        out[OUT_TOT] = (float)c * (float)BATCH;
    }

    const int wib  = threadIdx.x >> 5;            // warp in block, 0..3
    const int lane = threadIdx.x & 31;
    const int w    = blockIdx.x * 4 + wib;
    const int b    = w / CHUNKS;
    const int t0   = (w - b * CHUNKS) * CHLEN;

    const int half = lane >> 4;                   // which step of the pair
    const int rl   = lane & 15;
    const int row0 = 2 * rl;
    const int row1 = row0 + 1;

    const float om0 = 1.0f - sigm(tau_n[row0]);
    const float om1 = 1.0f - sigm(tau_n[row1]);

    // full 40-k masked, (1-beta)-scaled weight rows as packed f32x2 (80 regs)
    unsigned long long wp0[20], wp1[20];
    #pragma unroll
    for (int j = 0; j < 20; ++j) {
        int k = 2 * j;
        wp0[j] = packf2(W1[row0 * NI + k]     * mask[row0 * NI + k]     * om0,
                        W1[row0 * NI + k + 1] * mask[row0 * NI + k + 1] * om0);
        wp1[j] = packf2(W1[row1 * NI + k]     * mask[row1 * NI + k]     * om1,
                        W1[row1 * NI + k + 1] * mask[row1 * NI + k + 1] * om1);
    }

    // this lane's step within each pair: t0 + 2i + half
    const ulonglong2* xp = reinterpret_cast<const ulonglong2*>(
        x + ((size_t)b * TSTEPS + t0 + half) * NI);   // +2 steps = +8 ulonglong2
    float* cp = g_cur + ((size_t)b * TSTEPS + t0) * NR;

    #pragma unroll 2
    for (int i = 0; i < NPAIR; ++i) {
        // 10 independent uniform-address LDG.128 (batched across unroll)
        ulonglong2 v0 = xp[0];
        ulonglong2 v1 = xp[1];
        ulonglong2 v2 = xp[2];
        ulonglong2 v3 = xp[3];
        ulonglong2 v4 = xp[4];
        ulonglong2 v5 = xp[5];
        ulonglong2 v6 = xp[6];
        ulonglong2 v7 = xp[7];
        ulonglong2 v8 = xp[8];
        ulonglong2 v9 = xp[9];
        xp += 10;   // advance 2 steps (80 floats)

        unsigned long long a0 = 0ull, a1 = 0ull, b0 = 0ull, b1 = 0ull;
        fma2(a0, wp0[0],  v0.x); fma2(a1, wp0[1],  v0.y);
        fma2(b0, wp1[0],  v0.x); fma2(b1, wp1[1],  v0.y);
        fma2(a0, wp0[2],  v1.x); fma2(a1, wp0[3],  v1.y);
        fma2(b0, wp1[2],  v1.x); fma2(b1, wp1[3],  v1.y);
        fma2(a0, wp0[4],  v2.x); fma2(a1, wp0[5],  v2.y);
        fma2(b0, wp1[4],  v2.x); fma2(b1, wp1[5],  v2.y);
        fma2(a0, wp0[6],  v3.x); fma2(a1, wp0[7],  v3.y);
        fma2(b0, wp1[6],  v3.x); fma2(b1, wp1[7],  v3.y);
        fma2(a0, wp0[8],  v4.x); fma2(a1, wp0[9],  v4.y);
        fma2(b0, wp1[8],  v4.x); fma2(b1, wp1[9],  v4.y);
        fma2(a0, wp0[10], v5.x); fma2(a1, wp0[11], v5.y);
        fma2(b0, wp1[10], v5.x); fma2(b1, wp1[11], v5.y);
        fma2(a0, wp0[12], v6.x); fma2(a1, wp0[13], v6.y);
        fma2(b0, wp1[12], v6.x); fma2(b1, wp1[13], v6.y);
        fma2(a0, wp0[14], v7.x); fma2(a1, wp0[15], v7.y);
        fma2(b0, wp1[14], v7.x); fma2(b1, wp1[15], v7.y);
        fma2(a0, wp0[16], v8.x); fma2(a1, wp0[17], v8.y);
        fma2(b0, wp1[16], v8.x); fma2(b1, wp1[17], v8.y);
        fma2(a0, wp0[18], v9.x); fma2(a1, wp0[19], v9.y);
        fma2(b0, wp1[18], v9.x); fma2(b1, wp1[19], v9.y);

        float s0, s1, s2, s3, s4, s5, s6, s7;
        unpackf2(a0, s0, s1);
        unpackf2(a1, s2, s3);
        unpackf2(b0, s4, s5);
        unpackf2(b1, s6, s7);
        float h0 = (s0 + s1) + (s2 + s3);
        float h1 = (s4 + s5) + (s6 + s7);

        // both steps of the pair stored by one warp-wide STG.64 (256B)
        *reinterpret_cast<float2*>(cp + (2 * i + half) * NR + row0)
            = make_float2(h0, h1);
    }
}

// ---------------- Kernel B: pure state recurrence ---------------------------
// lane gl (0..7) of each 8-lane group owns rows 4gl..4gl+3 = neurons 2gl,2gl+1
#define PD 20

__global__ __launch_bounds__(128) void recur_kernel(
    const float* __restrict__ tau_m,  // [NH]
    const float* __restrict__ tau_n)  // [NR]
{
    const int lane = threadIdx.x & 31;
    const int warp = (blockIdx.x * 128 + threadIdx.x) >> 5;
    const int g    = lane >> 3;
    const int gl   = lane & 7;
    const int b    = warp * 4 + g;
    const unsigned FULL = 0xffffffffu;

    const float4 tn4 = *reinterpret_cast<const float4*>(tau_n + gl * 4);
    const float be0 = sigm(tn4.x), be1 = sigm(tn4.y);
    const float be2 = sigm(tn4.z), be3 = sigm(tn4.w);
    const float2 tm2 = *reinterpret_cast<const float2*>(tau_m + gl * 2);
    const float alA = sigm(tm2.x), omA = 1.0f - alA;
    const float alB = sigm(tm2.y), omB = 1.0f - alB;

    const float4* cp = reinterpret_cast<const float4*>(g_cur)
                     + (size_t)b * TSTEPS * (NR / 4) + gl;
    uint2* bp = g_ball + (size_t)warp * TSTEPS;

    float4 pc[PD];
    #pragma unroll
    for (int j = 0; j < PD; ++j) pc[j] = cp[(size_t)j * (NR / 4)];

    float d0 = 0.f, d1 = 0.f, d2 = 0.f, d3 = 0.f;
    float memA = 0.f, memB = 0.f, spkA = 0.f, spkB = 0.f;

    for (int tt = 0; tt < TSTEPS; tt += PD) {
        #pragma unroll
        for (int u = 0; u < PD; ++u) {
            const int t = tt + u;
            float4 v = pc[u];
            const int tn_ = t + PD;
            if (tn_ < TSTEPS) pc[u] = cp[(size_t)tn_ * (NR / 4)];

            d0 = fmaf(be0, d0, v.x);
            d1 = fmaf(be1, d1, v.y);
            d2 = fmaf(be2, d2, v.z);
            d3 = fmaf(be3, d3, v.w);
            float lA = d0 + d1;
            float lB = d2 + d3;

            memA = fmaf(alA, memA - spkA, omA * lA);
            memB = fmaf(alB, memB - spkB, omB * lB);
            bool sA = memA > 1.0f;               // VTH = 1
            bool sB = memB > 1.0f;
            spkA = sA ? 1.0f : 0.0f;
            spkB = sB ? 1.0f : 0.0f;

            unsigned bA = __ballot_sync(FULL, sA);
            unsigned bB = __ballot_sync(FULL, sB);
            if (lane == 0) bp[t] = make_uint2(bA, bB);
        }
    }
}

// ---------------- Kernel C: parallel logits + CE/accuracy -------------------
#define CBLK 256

__global__ __launch_bounds__(CBLK) void logits_kernel(
    const int*   __restrict__ target, // [B, T]
    const float* __restrict__ W2,     // [NO, NH]
    const float* __restrict__ b2,     // [NO]
    float*       __restrict__ out)
{
    __shared__ float LA0[256], LA1[256], LB0[256], LB1[256];
    __shared__ float redL[CBLK / 32], redC[CBLK / 32];

    {
        int m = threadIdx.x;
        if (m < 256) {
            float a0 = 0.f, a1 = 0.f, c0 = 0.f, c1 = 0.f;
            #pragma unroll
            for (int gl = 0; gl < 8; ++gl) {
                if ((m >> gl) & 1) {
                    a0 += W2[2 * gl];
                    a1 += W2[NH + 2 * gl];
                    c0 += W2[2 * gl + 1];
                    c1 += W2[NH + 2 * gl + 1];
                }
            }
            LA0[m] = a0; LA1[m] = a1; LB0[m] = c0; LB1[m] = c1;
        }
    }
    __syncthreads();

    const float b20 = b2[0], b21 = b2[1];
    const int total = BATCH * TSTEPS;
    const int stride = gridDim.x * CBLK;

    float lossAcc = 0.0f;
    int   corrAcc = 0;

    for (int i = blockIdx.x * CBLK + threadIdx.x; i < total; i += stride) {
        int b = i / TSTEPS;
        int t = i - b * TSTEPS;
        uint2 ball = g_ball[(size_t)(b >> 2) * TSTEPS + t];
        int sh = (b & 3) * 8;
        int a = (ball.x >> sh) & 255;
        int c = (ball.y >> sh) & 255;
        float l0 = b20 + LA0[a] + LB0[c];
        float l1 = b21 + LA1[a] + LB1[c];
        out[OUT_D2 + 2 * (size_t)i]     = l0;
        out[OUT_D2 + 2 * (size_t)i + 1] = l1;

        bool flag = (t > 10) && (((t - 10) % 15) > 5);
        if (flag) {
            int tgt = target[i];
            float z  = l1 - l0;
            float p1 = 1.0f / (1.0f + __expf(-z));
            float p0 = 1.0f - p1;
            float lse = __logf(__expf(p0) + __expf(p1));  // double-softmax CE
            float ptgt = tgt ? p1 : p0;
            lossAcc += (lse - ptgt);
            corrAcc += (((z > 0.0f) ? 1 : 0) == tgt);
        }
    }

    const unsigned FULL = 0xffffffffu;
    float corrF = (float)corrAcc;
    #pragma unroll
    for (int o = 16; o > 0; o >>= 1) {
        lossAcc += __shfl_xor_sync(FULL, lossAcc, o);
        corrF   += __shfl_xor_sync(FULL, corrF, o);
    }
    int wid = threadIdx.x >> 5;
    if ((threadIdx.x & 31) == 0) { redL[wid] = lossAcc; redC[wid] = corrF; }
    __syncthreads();
    if (threadIdx.x == 0) {
        float L = 0.f, C = 0.f;
        #pragma unroll
        for (int k = 0; k < CBLK / 32; ++k) { L += redL[k]; C += redC[k]; }
        atomicAdd(&out[OUT_LOSS], L * (1.0f / (float)BATCH));
        atomicAdd(&out[OUT_CORR], C);
    }
}

extern "C" void kernel_launch(void* const* d_in, const int* in_sizes, int n_in,
                              void* d_out, int out_size) {
    const float* x      = (const float*)d_in[0];
    const int*   target = (const int*)  d_in[1];
    const float* W1     = (const float*)d_in[2];
    const float* tau_m  = (const float*)d_in[3];
    const float* tau_n  = (const float*)d_in[4];
    const float* mask   = (const float*)d_in[5];
    const float* W2     = (const float*)d_in[6];
    const float* b2     = (const float*)d_in[7];
    float* out = (float*)d_out;

    matvec_kernel<<<(BATCH * CHUNKS) / 4, 128>>>(x, W1, mask, tau_n, out);
    recur_kernel<<<(BATCH / 4) * 32 / 128, 128>>>(tau_m, tau_n);
    logits_kernel<<<1024, CBLK>>>(target, W2, b2, out);
}

// round 11
// speedup vs baseline: 2.4031x; 2.4031x over previous
#include <cuda_runtime.h>
#include <math.h>

#define BATCH 2048
#define TSTEPS 1000
#define NI 40
#define NH 16
#define NR 32
#define NO 2

#define NTILES 32                 // 32-step tiles per batch: 31 full + 1x8
#define OUT_LOSS 0
#define OUT_D2   1
#define OUT_CORR (1 + (size_t)BATCH * TSTEPS * NO)
#define OUT_TOT  (OUT_CORR + 1)

// 262 MB scratch: pre-scaled dendritic currents cur[b][t][r] (x (1-beta_r))
__device__ __align__(16) float g_cur[(size_t)BATCH * TSTEPS * NR];
// 4 MB scratch: packed spike ballots per recur-warp (4 batches) per step
__device__ __align__(16) uint2 g_ball[(size_t)(BATCH / 4) * TSTEPS];
// staging for the masked/scaled weights, copied into constant memory
__device__ unsigned long long g_wbuf[NR * 20];
// constant-bank weights: c_w[r*20 + j] = packed f32x2 (w[r][2j], w[r][2j+1])
__constant__ unsigned long long c_w[NR * 20];

__device__ __forceinline__ void fma2(unsigned long long& acc,
                                     unsigned long long a,
                                     unsigned long long b) {
    asm("fma.rn.f32x2 %0, %1, %2, %3;" : "=l"(acc) : "l"(a), "l"(b), "l"(acc));
}
__device__ __forceinline__ unsigned long long packf2(float lo, float hi) {
    unsigned long long r;
    asm("mov.b64 %0, {%1, %2};" : "=l"(r) : "f"(lo), "f"(hi));
    return r;
}
__device__ __forceinline__ void unpackf2(unsigned long long v, float& lo, float& hi) {
    asm("mov.b64 {%0, %1}, %2;" : "=f"(lo), "=f"(hi) : "l"(v));
}
__device__ __forceinline__ float sigm(float v) { return 1.0f / (1.0f + expf(-v)); }

// ---- prep: masked, (1-beta)-scaled, packed weights + output scalar init ----
__global__ void prep_kernel(const float* __restrict__ W1,
                            const float* __restrict__ mask,
                            const float* __restrict__ tau_n,
                            float* __restrict__ out) {
    int r = threadIdx.x;  // one lane per row
    if (r == 0) {
        out[OUT_LOSS] = 0.0f;
        int c = 0;
        for (int t = 0; t < TSTEPS; ++t)
            if (t > 10 && ((t - 10) % 15) > 5) c++;
        out[OUT_CORR] = 0.0f;
        out[OUT_TOT] = (float)c * (float)BATCH;
    }
    float om = 1.0f - sigm(tau_n[r]);
    #pragma unroll
    for (int j = 0; j < 20; ++j) {
        int k = 2 * j;
        g_wbuf[r * 20 + j] =
            packf2(W1[r * NI + k]     * mask[r * NI + k]     * om,
                   W1[r * NI + k + 1] * mask[r * NI + k + 1] * om);
    }
}

// ---------------- Kernel A: matvec, one lane per timestep -------------------
// warp w: batch b = w/32, tile = w%32 -> steps [32*tile, 32*tile+nsteps).
// Lane s computes cur[b][t0+s][0..31] with weights from the constant bank.
// x flows GMEM -(coalesced LDG)-> smem -(conflict-free per-lane LDS)-> regs;
// outputs flow regs -(conflict-free STS)-> smem -(coalesced STG)-> GMEM.
__global__ __launch_bounds__(128) void matvec_kernel(
    const float* __restrict__ x)     // [B, T, NI]
{
    const int wib  = threadIdx.x >> 5;
    const int lane = threadIdx.x & 31;
    const int w    = blockIdx.x * 4 + wib;
    const int b    = w >> 5;
    const int tile = w & 31;
    const int t0   = tile * 32;
    const int nsteps = (tile == 31) ? (TSTEPS - 31 * 32) : 32;   // 8 or 32

    // padded rows: 44 floats (176B) per step; stride 11 x 16B groups -> cf
    __shared__ __align__(16) float sb[4][32 * 44];
    float* sbuf = sb[wib];

    // ---- stage x tile: coalesced GMEM -> transposed smem rows ----
    const float4* xs = reinterpret_cast<const float4*>(
        x + ((size_t)b * TSTEPS + t0) * NI);
    const int nchunk = nsteps * 10;               // 16B chunks in tile
    #pragma unroll
    for (int i = 0; i < 10; ++i) {
        int c = i * 32 + lane;
        if (c < nchunk) {
            float4 v = xs[c];
            int s = c / 10;                        // step row
            int q = c - s * 10;                    // 16B group in row
            *reinterpret_cast<float4*>(&sbuf[s * 44 + q * 4]) = v;
        }
    }
    __syncwarp();

    // ---- per-lane read of own step's 160B (conflict-free LDS.128) ----
    unsigned long long xr[20];
    {
        const ulonglong2* xrow =
            reinterpret_cast<const ulonglong2*>(&sbuf[lane * 44]);
        #pragma unroll
        for (int j2 = 0; j2 < 10; ++j2) {
            ulonglong2 t = xrow[j2];
            xr[2 * j2]     = t.x;
            xr[2 * j2 + 1] = t.y;
        }
    }
    __syncwarp();

    // ---- compute 32 rows; weights from constant bank (uniform index) ----
    #pragma unroll
    for (int rg = 0; rg < 8; ++rg) {
        float4 o;
        #pragma unroll
        for (int rr = 0; rr < 4; ++rr) {
            const int r = rg * 4 + rr;
            unsigned long long acc0 = 0ull, acc1 = 0ull;
            #pragma unroll
            for (int j = 0; j < 10; ++j) {
                fma2(acc0, c_w[r * 20 + j],      xr[j]);
                fma2(acc1, c_w[r * 20 + 10 + j], xr[10 + j]);
            }
            float s0, s1, s2, s3;
            unpackf2(acc0, s0, s1);
            unpackf2(acc1, s2, s3);
            reinterpret_cast<float*>(&o)[rr] = (s0 + s1) + (s2 + s3);
        }
        if (lane < nsteps)
            *reinterpret_cast<float4*>(&sbuf[lane * 44 + rg * 4]) = o;
    }
    __syncwarp();

    // ---- store tile: transposed smem -> coalesced GMEM ----
    float4* cp = reinterpret_cast<float4*>(
        g_cur + ((size_t)b * TSTEPS + t0) * NR);
    const int ochunk = nsteps * 8;                // 16B chunks out
    #pragma unroll
    for (int i = 0; i < 8; ++i) {
        int c = i * 32 + lane;
        if (c < ochunk) {
            int s = c >> 3;
            int q = c & 7;
            cp[c] = *reinterpret_cast<float4*>(&sbuf[s * 44 + q * 4]);
        }
    }
}

// ---------------- Kernel B: pure state recurrence ---------------------------
// lane gl (0..7) of each 8-lane group owns rows 4gl..4gl+3 = neurons 2gl,2gl+1
#define PD 20

__global__ __launch_bounds__(128) void recur_kernel(
    const float* __restrict__ tau_m,  // [NH]
    const float* __restrict__ tau_n)  // [NR]
{
    const int lane = threadIdx.x & 31;
    const int warp = (blockIdx.x * 128 + threadIdx.x) >> 5;
    const int g    = lane >> 3;
    const int gl   = lane & 7;
    const int b    = warp * 4 + g;
    const unsigned FULL = 0xffffffffu;

    const float4 tn4 = *reinterpret_cast<const float4*>(tau_n + gl * 4);
    const float be0 = sigm(tn4.x), be1 = sigm(tn4.y);
    const float be2 = sigm(tn4.z), be3 = sigm(tn4.w);
    const float2 tm2 = *reinterpret_cast<const float2*>(tau_m + gl * 2);
    const float alA = sigm(tm2.x), omA = 1.0f - alA;
    const float alB = sigm(tm2.y), omB = 1.0f - alB;

    const float4* cp = reinterpret_cast<const float4*>(g_cur)
                     + (size_t)b * TSTEPS * (NR / 4) + gl;
    uint2* bp = g_ball + (size_t)warp * TSTEPS;

    float4 pc[PD];
    #pragma unroll
    for (int j = 0; j < PD; ++j) pc[j] = cp[(size_t)j * (NR / 4)];

    float d0 = 0.f, d1 = 0.f, d2 = 0.f, d3 = 0.f;
    float memA = 0.f, memB = 0.f, spkA = 0.f, spkB = 0.f;

    for (int tt = 0; tt < TSTEPS; tt += PD) {
        #pragma unroll
        for (int u = 0; u < PD; ++u) {
            const int t = tt + u;
            float4 v = pc[u];
            const int tn_ = t + PD;
            if (tn_ < TSTEPS) pc[u] = cp[(size_t)tn_ * (NR / 4)];

            d0 = fmaf(be0, d0, v.x);
            d1 = fmaf(be1, d1, v.y);
            d2 = fmaf(be2, d2, v.z);
            d3 = fmaf(be3, d3, v.w);
            float lA = d0 + d1;
            float lB = d2 + d3;

            memA = fmaf(alA, memA - spkA, omA * lA);
            memB = fmaf(alB, memB - spkB, omB * lB);
            bool sA = memA > 1.0f;               // VTH = 1
            bool sB = memB > 1.0f;
            spkA = sA ? 1.0f : 0.0f;
            spkB = sB ? 1.0f : 0.0f;

            unsigned bA = __ballot_sync(FULL, sA);
            unsigned bB = __ballot_sync(FULL, sB);
            if (lane == 0) bp[t] = make_uint2(bA, bB);
        }
    }
}

// ---------------- Kernel C: parallel logits + CE/accuracy -------------------
#define CBLK 256

__global__ __launch_bounds__(CBLK) void logits_kernel(
    const int*   __restrict__ target, // [B, T]
    const float* __restrict__ W2,     // [NO, NH]
    const float* __restrict__ b2,     // [NO]
    float*       __restrict__ out)
{
    __shared__ float LA0[256], LA1[256], LB0[256], LB1[256];
    __shared__ float redL[CBLK / 32], redC[CBLK / 32];

    {
        int m = threadIdx.x;
        if (m < 256) {
            float a0 = 0.f, a1 = 0.f, c0 = 0.f, c1 = 0.f;
            #pragma unroll
            for (int gl = 0; gl < 8; ++gl) {
                if ((m >> gl) & 1) {
                    a0 += W2[2 * gl];
                    a1 += W2[NH + 2 * gl];
                    c0 += W2[2 * gl + 1];
                    c1 += W2[NH + 2 * gl + 1];
                }
            }
            LA0[m] = a0; LA1[m] = a1; LB0[m] = c0; LB1[m] = c1;
        }
    }
    __syncthreads();

    const float b20 = b2[0], b21 = b2[1];
    const int total = BATCH * TSTEPS;
    const int stride = gridDim.x * CBLK;

    float lossAcc = 0.0f;
    int   corrAcc = 0;

    for (int i = blockIdx.x * CBLK + threadIdx.x; i < total; i += stride) {
        int b = i / TSTEPS;
        int t = i - b * TSTEPS;
        uint2 ball = g_ball[(size_t)(b >> 2) * TSTEPS + t];
        int sh = (b & 3) * 8;
        int a = (ball.x >> sh) & 255;
        int c = (ball.y >> sh) & 255;
        float l0 = b20 + LA0[a] + LB0[c];
        float l1 = b21 + LA1[a] + LB1[c];
        out[OUT_D2 + 2 * (size_t)i]     = l0;
        out[OUT_D2 + 2 * (size_t)i + 1] = l1;

        bool flag = (t > 10) && (((t - 10) % 15) > 5);
        if (flag) {
            int tgt = target[i];
            float z  = l1 - l0;
            float p1 = 1.0f / (1.0f + __expf(-z));
            float p0 = 1.0f - p1;
            float lse = __logf(__expf(p0) + __expf(p1));  // double-softmax CE
            float ptgt = tgt ? p1 : p0;
            lossAcc += (lse - ptgt);
            corrAcc += (((z > 0.0f) ? 1 : 0) == tgt);
        }
    }

    const unsigned FULL = 0xffffffffu;
    float corrF = (float)corrAcc;
    #pragma unroll
    for (int o = 16; o > 0; o >>= 1) {
        lossAcc += __shfl_xor_sync(FULL, lossAcc, o);
        corrF   += __shfl_xor_sync(FULL, corrF, o);
    }
    int wid = threadIdx.x >> 5;
    if ((threadIdx.x & 31) == 0) { redL[wid] = lossAcc; redC[wid] = corrF; }
    __syncthreads();
    if (threadIdx.x == 0) {
        float L = 0.f, C = 0.f;
        #pragma unroll
        for (int k = 0; k < CBLK / 32; ++k) { L += redL[k]; C += redC[k]; }
        atomicAdd(&out[OUT_LOSS], L * (1.0f / (float)BATCH));
        atomicAdd(&out[OUT_CORR], C);
    }
}

extern "C" void kernel_launch(void* const* d_in, const int* in_sizes, int n_in,
                              void* d_out, int out_size) {
    const float* x      = (const float*)d_in[0];
    const int*   target = (const int*)  d_in[1];
    const float* W1     = (const float*)d_in[2];
    const float* tau_m  = (const float*)d_in[3];
    const float* tau_n  = (const float*)d_in[4];
    const float* mask   = (const float*)d_in[5];
    const float* W2     = (const float*)d_in[6];
    const float* b2     = (const float*)d_in[7];
    float* out = (float*)d_out;

    prep_kernel<<<1, 32>>>(W1, mask, tau_n, out);

    // device-to-device async copy of the packed weights into constant memory
    void* wsrc = nullptr;
    cudaGetSymbolAddress(&wsrc, g_wbuf);
    cudaMemcpyToSymbolAsync(c_w, wsrc, sizeof(unsigned long long) * NR * 20,
                            0, cudaMemcpyDeviceToDevice, 0);

    matvec_kernel<<<(BATCH * NTILES) / 4, 128>>>(x);
    recur_kernel<<<(BATCH / 4) * 32 / 128, 128>>>(tau_m, tau_n);
    logits_kernel<<<1024, CBLK>>>(target, W2, b2, out);
}